// round 7
// baseline (speedup 1.0000x reference)
#include <cuda_runtime.h>

#define N_SRC 50000
#define N_DST 50000
#define D     128
#define K     8

// Scratch (no allocations allowed)
__device__ int  g_counters[N_SRC + N_DST]; // [0,N_SRC)=out_deg, rest = neg cnt
__device__ int  g_ptr[N_DST + 1];
__device__ int2 g_pairs[N_DST * K];        // (src, weight-bits); (0,0) = pad;
                                           // pair0.src = -1 => fallback path
// Soft grid barrier state (zero-initialized; count returns to 0 after each use)
__device__ unsigned g_bar_count;
__device__ volatile unsigned g_bar_gen;

__device__ __forceinline__ void grid_barrier(unsigned nblocks) {
    __syncthreads();
    if (threadIdx.x == 0) {
        unsigned gen = g_bar_gen;
        __threadfence();                       // publish this block's writes
        unsigned t = atomicAdd(&g_bar_count, 1u);
        if (t == nblocks - 1u) {
            g_bar_count = 0u;
            __threadfence();
            g_bar_gen = gen + 1u;              // release
        } else {
            while (g_bar_gen == gen) { }       // volatile L2 spin
        }
        __threadfence();
    }
    __syncthreads();
}

__global__ void __launch_bounds__(256, 4)
mega_kernel(const float* __restrict__ h_src,
            const float* __restrict__ unif,
            const int* __restrict__ src_idx,
            const int* __restrict__ dst_idx,
            const int* __restrict__ category,
            float* __restrict__ out, int E) {
    const unsigned nblocks  = gridDim.x;
    const int nthreads = (int)(gridDim.x * blockDim.x);
    const int tid0     = (int)(blockIdx.x * blockDim.x + threadIdx.x);
    const int lane     = threadIdx.x & 31;
    const int gwarp0   = tid0 >> 5;
    const int nwarps   = nthreads >> 5;

    // ---- Phase 0: zero counters --------------------------------------------
    for (int i = tid0; i < N_SRC + N_DST; i += nthreads)
        g_counters[i] = 0;
    grid_barrier(nblocks);

    // ---- Phase 1: out-degree histogram + neg counter + CSR ptr scan --------
    for (int e = tid0; e < E; e += nthreads) {
        int s = __ldg(&src_idx[e]);
        atomicAdd(&g_counters[s], 1);
        int cur = __ldg(&dst_idx[e]);
        if (__ldg(&category[s]) == -1) atomicAdd(&g_counters[N_SRC + cur], 1);
        int prev = (e == 0) ? -1 : __ldg(&dst_idx[e - 1]);
        for (int d = prev + 1; d <= cur; ++d) g_ptr[d] = e;
        if (e == E - 1)
            for (int d = cur + 1; d <= N_DST; ++d) g_ptr[d] = E;
    }
    grid_barrier(nblocks);

    // ---- Phase 2: sampling resolution + octet dedup -------------------------
    // N_DST*K = 400000 is divisible by 32, so warps are always full here.
    for (int t = gwarp0 * 32 + lane; t < N_DST * K; t += nwarps * 32) {
        int n = t >> 3;
        int k = t & 7;
        int p0 = __ldcg(&g_ptr[n]);
        int p1 = __ldcg(&g_ptr[n + 1]);
        int deg = p1 - p0;
        bool small = (deg <= K);
        bool esc   = !small && (__ldcg(&g_counters[N_SRC + n]) > 0);

        int src = 0;
        float w = 0.f;
        if (!small && !esc) {
            float fdeg = (float)deg;
            float u = __ldg(&unif[t]);
            int off = min((int)floorf(u * fdeg), deg - 1);
            int eid = min(p0 + off, E - 1);
            src = __ldg(&src_idx[eid]);
            w = rsqrtf((float)max(__ldcg(&g_counters[src]), 1)) * rsqrtf(fdeg);
        } else if (small && k < deg) {
            src = __ldg(&src_idx[p0 + k]);
            w = rsqrtf((float)max(__ldcg(&g_counters[src]), 1)) *
                rsqrtf((float)max(deg, 1));
        }

        // Octet dedup (ALL lanes participate; esc lanes carry zeros)
        int base = lane & ~7;
        float wsum = 0.f;
        int first = k;
        #pragma unroll
        for (int j = 0; j < K; ++j) {
            int   sj = __shfl_sync(0xffffffffu, src, base + j);
            float wj = __shfl_sync(0xffffffffu, w,   base + j);
            if (sj == src) {
                wsum += wj;
                first = min(first, j);
            }
        }
        if (esc) {
            if (k == 0) g_pairs[t] = make_int2(-1, 0);
        } else {
            g_pairs[t] = (first == k) ? make_int2(src, __float_as_int(wsum))
                                      : make_int2(0, 0);
        }
    }
    grid_barrier(nblocks);

    // ---- Phase 3: one warp per dst node, gather + store ---------------------
    for (int n = gwarp0; n < N_DST; n += nwarps) {
        const int4* pb = (const int4*)(g_pairs + n * K);
        int4 q0 = __ldcg(&pb[0]);
        int4 q1 = __ldcg(&pb[1]);
        int4 q2 = __ldcg(&pb[2]);
        int4 q3 = __ldcg(&pb[3]);

        float4 acc = make_float4(0.f, 0.f, 0.f, 0.f);

        if (q0.x >= 0) {
            int   srcs[K] = {q0.x, q0.z, q1.x, q1.z, q2.x, q2.z, q3.x, q3.z};
            float ws[K]   = {__int_as_float(q0.y), __int_as_float(q0.w),
                             __int_as_float(q1.y), __int_as_float(q1.w),
                             __int_as_float(q2.y), __int_as_float(q2.w),
                             __int_as_float(q3.y), __int_as_float(q3.w)};
            #pragma unroll
            for (int k = 0; k < K; ++k) {
                const float4* row = (const float4*)(h_src + (long long)srcs[k] * D);
                float4 v = __ldg(&row[lane]);
                float w = ws[k];
                acc.x += v.x * w; acc.y += v.y * w; acc.z += v.z * w; acc.w += v.w * w;
            }
            ((float4*)(out + (long long)n * D))[lane] = acc;
        } else {
            // Escape hatch (neg>0 && deg>K): full reduction over all edges.
            int p0 = __ldcg(&g_ptr[n]);
            int p1 = __ldcg(&g_ptr[n + 1]);
            int deg = p1 - p0;
            for (int e = p0; e < p1; ++e) {
                int s = __ldg(&src_idx[e]);
                float w = rsqrtf((float)max(__ldcg(&g_counters[s]), 1));
                const float4* row = (const float4*)(h_src + (long long)s * D);
                float4 v = __ldg(&row[lane]);
                acc.x += v.x * w; acc.y += v.y * w; acc.z += v.z * w; acc.w += v.w * w;
            }
            float innorm = rsqrtf((float)max(deg, 1));
            float4 o;
            o.x = acc.x * innorm; o.y = acc.y * innorm;
            o.z = acc.z * innorm; o.w = acc.w * innorm;
            ((float4*)(out + (long long)n * D))[lane] = o;
        }
    }
}

extern "C" void kernel_launch(void* const* d_in, const int* in_sizes, int n_in,
                              void* d_out, int out_size) {
    const float* h_src    = (const float*)d_in[0];
    // d_in[1] = h_dst : unused by the reference computation
    const float* unif     = (const float*)d_in[2];
    const int*   src_idx  = (const int*)d_in[3];
    const int*   dst_idx  = (const int*)d_in[4];
    const int*   category = (const int*)d_in[5];
    float* out = (float*)d_out;

    int E = in_sizes[3];

    // Deadlock-safe persistent grid: all blocks simultaneously resident.
    // Host-side queries run at capture time only (free at replay).
    int dev = 0, sms = 0, per_sm = 0;
    cudaGetDevice(&dev);
    cudaDeviceGetAttribute(&sms, cudaDevAttrMultiProcessorCount, dev);
    cudaOccupancyMaxActiveBlocksPerMultiprocessor(&per_sm, mega_kernel, 256, 0);
    if (per_sm < 1) per_sm = 1;
    if (per_sm > 4) per_sm = 4;   // matches __launch_bounds__(256,4)
    int blocks = sms * per_sm;
    if (blocks < 1) blocks = 148 * 2;

    mega_kernel<<<blocks, 256>>>(h_src, unif, src_idx, dst_idx, category,
                                 out, E);
}

// round 8
// speedup vs baseline: 1.2821x; 1.2821x over previous
#include <cuda_runtime.h>

#define N_SRC 50000
#define N_DST 50000
#define D     128
#define K     8

// Scratch (no allocations allowed)
__device__ int  g_counters[N_SRC + N_DST]; // [0,N_SRC)=out_deg, rest = neg cnt
__device__ int  g_anyneg;                  // any category[i] == -1 ?
__device__ int  g_ptr[N_DST + 1];
__device__ int2 g_pairs[N_DST * K];        // (src, weight-bits); (0,0) = pad;
                                           // pair0.src = -1 => fallback path

// Kernel 0: zero counters + flag, and scan category for -1 (coalesced 200 KB).
// Replaces the memset node — same graph node count as before.
__global__ void __launch_bounds__(256)
zero_scan_kernel(const int* __restrict__ category, int n_src) {
    int i = blockIdx.x * blockDim.x + threadIdx.x;
    if (i < N_SRC + N_DST) g_counters[i] = 0;
    if (i == 0) g_anyneg = 0;
    if (i < n_src && __ldg(&category[i]) == -1)
        g_anyneg = 1;   // only value ever stored is 1: plain racy store is safe
}

// Kernel 1: out-degree histogram + CSR ptr boundary scan. The category gather
// + neg atomics (escape hatch feed) run ONLY if some category == -1.
__global__ void __launch_bounds__(256)
count_kernel(const int* __restrict__ src_idx,
             const int* __restrict__ dst_idx,
             const int* __restrict__ category, int E) {
    int e = blockIdx.x * blockDim.x + threadIdx.x;
    if (e >= E) return;
    int s = __ldg(&src_idx[e]);
    atomicAdd(&g_counters[s], 1);
    int cur = __ldg(&dst_idx[e]);
    if (g_anyneg) {                               // uniform branch; normally 0
        if (__ldg(&category[s]) == -1)
            atomicAdd(&g_counters[N_SRC + cur], 1);
    }
    int prev = (e == 0) ? -1 : __ldg(&dst_idx[e - 1]);
    for (int d = prev + 1; d <= cur; ++d) g_ptr[d] = e;
    if (e == E - 1)
        for (int d = cur + 1; d <= N_DST; ++d) g_ptr[d] = E;
}

// Kernel 2: resolve sampling per (node,k), one thread each (400k threads hide
// the ptr->unif->src_idx->out_deg chain). Octet dedup via shuffles: duplicate
// sampled srcs merged (first occurrence keeps summed weight, rest become
// (0,0) pads -> L1-resident row-0 gathers in main). Both norms folded in.
// Fallback nodes (neg>0 && deg>K, never on sane data) get src=-1 sentinel.
__global__ void __launch_bounds__(256)
prep_kernel(const float* __restrict__ unif,
            const int* __restrict__ src_idx, int E) {
    int t = blockIdx.x * blockDim.x + threadIdx.x;
    if (t >= N_DST * K) return;
    int n = t >> 3;
    int k = t & 7;
    int p0 = __ldg(&g_ptr[n]);
    int p1 = __ldg(&g_ptr[n + 1]);
    int deg = p1 - p0;
    bool small = (deg <= K);
    bool esc   = !small && (__ldg(&g_counters[N_SRC + n]) > 0);

    int src = 0;
    float w = 0.f;
    if (!small && !esc) {
        float fdeg = (float)deg;
        float u = __ldg(&unif[t]);
        int off = min((int)floorf(u * fdeg), deg - 1);
        int eid = min(p0 + off, E - 1);
        src = __ldg(&src_idx[eid]);
        w = rsqrtf((float)max(__ldg(&g_counters[src]), 1)) * rsqrtf(fdeg);
    } else if (small && k < deg) {
        src = __ldg(&src_idx[p0 + k]);
        w = rsqrtf((float)max(__ldg(&g_counters[src]), 1)) *
            rsqrtf((float)max(deg, 1));
    }

    // Octet dedup — ALL lanes participate in the shuffles (no early return).
    int lane = threadIdx.x & 31;
    int base = lane & ~7;
    float wsum = 0.f;
    int first = k;
    #pragma unroll
    for (int j = 0; j < K; ++j) {
        int   sj = __shfl_sync(0xffffffffu, src, base + j);
        float wj = __shfl_sync(0xffffffffu, w,   base + j);
        if (sj == src) {
            wsum += wj;
            first = min(first, j);
        }
    }
    if (esc) {
        if (k == 0) g_pairs[t] = make_int2(-1, 0);
    } else {
        g_pairs[t] = (first == k) ? make_int2(src, __float_as_int(wsum))
                                  : make_int2(0, 0);
    }
}

// Kernel 3: one warp per dst node, barrier-free. The ONLY dependent load is
// the 4 broadcast int4 pair loads; the path flag rides in pair0.x's sign.
__global__ void __launch_bounds__(256)
main_kernel(const float* __restrict__ h_src,
            const int* __restrict__ src_idx,
            float* __restrict__ out) {
    int warp = (blockIdx.x * blockDim.x + threadIdx.x) >> 5;  // grid exact
    int lane = threadIdx.x & 31;
    int n = warp;

    const int4* pb = (const int4*)(g_pairs + n * K);
    int4 q0 = __ldg(&pb[0]);
    int4 q1 = __ldg(&pb[1]);
    int4 q2 = __ldg(&pb[2]);
    int4 q3 = __ldg(&pb[3]);

    float4 acc = make_float4(0.f, 0.f, 0.f, 0.f);

    if (q0.x >= 0) {
        int   srcs[K] = {q0.x, q0.z, q1.x, q1.z, q2.x, q2.z, q3.x, q3.z};
        float ws[K]   = {__int_as_float(q0.y), __int_as_float(q0.w),
                         __int_as_float(q1.y), __int_as_float(q1.w),
                         __int_as_float(q2.y), __int_as_float(q2.w),
                         __int_as_float(q3.y), __int_as_float(q3.w)};
        #pragma unroll
        for (int k = 0; k < K; ++k) {
            const float4* row = (const float4*)(h_src + (long long)srcs[k] * D);
            float4 v = __ldg(&row[lane]);
            float w = ws[k];
            acc.x += v.x * w; acc.y += v.y * w; acc.z += v.z * w; acc.w += v.w * w;
        }
        ((float4*)(out + (long long)n * D))[lane] = acc;
    } else {
        // Escape hatch (neg>0 && deg>K): full reduction over all edges.
        int p0 = __ldg(&g_ptr[n]);
        int p1 = __ldg(&g_ptr[n + 1]);
        int deg = p1 - p0;
        for (int e = p0; e < p1; ++e) {
            int s = __ldg(&src_idx[e]);
            float w = rsqrtf((float)max(__ldg(&g_counters[s]), 1));
            const float4* row = (const float4*)(h_src + (long long)s * D);
            float4 v = __ldg(&row[lane]);
            acc.x += v.x * w; acc.y += v.y * w; acc.z += v.z * w; acc.w += v.w * w;
        }
        float innorm = rsqrtf((float)max(deg, 1));
        float4 o;
        o.x = acc.x * innorm; o.y = acc.y * innorm;
        o.z = acc.z * innorm; o.w = acc.w * innorm;
        ((float4*)(out + (long long)n * D))[lane] = o;
    }
}

extern "C" void kernel_launch(void* const* d_in, const int* in_sizes, int n_in,
                              void* d_out, int out_size) {
    const float* h_src    = (const float*)d_in[0];
    // d_in[1] = h_dst : unused by the reference computation
    const float* unif     = (const float*)d_in[2];
    const int*   src_idx  = (const int*)d_in[3];
    const int*   dst_idx  = (const int*)d_in[4];
    const int*   category = (const int*)d_in[5];
    float* out = (float*)d_out;

    int E = in_sizes[3];
    int n_src = in_sizes[5];

    zero_scan_kernel<<<(N_SRC + N_DST + 255) / 256, 256>>>(category, n_src);
    count_kernel<<<(E + 255) / 256, 256>>>(src_idx, dst_idx, category, E);
    prep_kernel<<<(N_DST * K + 255) / 256, 256>>>(unif, src_idx, E);
    main_kernel<<<(N_DST * 32) / 256, 256>>>(h_src, src_idx, out);
}

// round 9
// speedup vs baseline: 1.3774x; 1.0743x over previous
#include <cuda_runtime.h>

#define N_SRC 50000
#define N_DST 50000
#define D     128
#define K     8

// Scratch (no allocations allowed)
__device__ int  g_counters[N_SRC + N_DST]; // [0,N_SRC)=out_deg, rest = neg cnt
__device__ int  g_anyneg;                  // any category[i] == -1 ?
__device__ int  g_ptr[N_DST + 1];
__device__ int2 g_pairs[N_DST * K];        // (src, weight-bits); (0,0) = pad;
                                           // pair0.src = -1 => fallback path

// PDL: block until all prior grids in the dependency chain complete.
// With ProgrammaticStreamSerialization the grid LAUNCHES early (prologue
// overlaps the predecessor) but data consumption waits here.
__device__ __forceinline__ void pdl_wait() {
    asm volatile("griddepcontrol.wait;" ::: "memory");
}
__device__ __forceinline__ void pdl_fire() {
    asm volatile("griddepcontrol.launch_dependents;" ::: "memory");
}

// Kernel 0: zero counters + flag, and scan category for -1 (coalesced 200 KB).
__global__ void __launch_bounds__(256)
zero_scan_kernel(const int* __restrict__ category, int n_src) {
    int i = blockIdx.x * blockDim.x + threadIdx.x;
    if (i < N_SRC + N_DST) g_counters[i] = 0;
    if (i == 0) g_anyneg = 0;
    if (i < n_src && __ldg(&category[i]) == -1)
        g_anyneg = 1;   // only value ever stored is 1: plain racy store is safe
    pdl_fire();
}

// Kernel 1: out-degree histogram + CSR ptr boundary scan. Category gather +
// neg atomics (escape-hatch feed) run ONLY if some category == -1.
__global__ void __launch_bounds__(256)
count_kernel(const int* __restrict__ src_idx,
             const int* __restrict__ dst_idx,
             const int* __restrict__ category, int E) {
    int e = blockIdx.x * blockDim.x + threadIdx.x;
    // src/dst loads are pure-input reads: issue them BEFORE the PDL wait so
    // they overlap the predecessor's tail.
    int s = 0, cur = 0;
    bool act = (e < E);
    if (act) {
        s   = __ldg(&src_idx[e]);
        cur = __ldg(&dst_idx[e]);
    }
    // prev via intra-warp shuffle; only lane 0 (or e==0) needs a real load.
    int lane = threadIdx.x & 31;
    int prev = __shfl_up_sync(0xffffffffu, cur, 1);
    if (act && lane == 0) prev = (e == 0) ? -1 : __ldg(&dst_idx[e - 1]);

    pdl_wait();                    // counters are zeroed beyond this point
    if (!act) return;

    atomicAdd(&g_counters[s], 1);
    if (g_anyneg) {                               // uniform branch; normally 0
        if (__ldg(&category[s]) == -1)
            atomicAdd(&g_counters[N_SRC + cur], 1);
    }
    for (int d = prev + 1; d <= cur; ++d) g_ptr[d] = e;
    if (e == E - 1)
        for (int d = cur + 1; d <= N_DST; ++d) g_ptr[d] = E;
    pdl_fire();
}

// Kernel 2: resolve sampling per (node,k), one thread each. Octet dedup via
// shuffles; both norms folded into the weight; (0,0) pads stay L1-resident
// in main. Escape-hatch nodes (neg>0 && deg>K) get a src=-1 sentinel.
__global__ void __launch_bounds__(256)
prep_kernel(const float* __restrict__ unif,
            const int* __restrict__ src_idx, int E) {
    int t = blockIdx.x * blockDim.x + threadIdx.x;
    bool act = (t < N_DST * K);
    int n = t >> 3;
    int k = t & 7;
    float u = 0.f;
    if (act) u = __ldg(&unif[t]);  // pure input: prefetch before the wait

    pdl_wait();                    // g_ptr / g_counters valid beyond here
    if (!act) return;

    int p0 = __ldg(&g_ptr[n]);
    int p1 = __ldg(&g_ptr[n + 1]);
    int deg = p1 - p0;
    bool small = (deg <= K);
    bool esc   = !small && (__ldg(&g_counters[N_SRC + n]) > 0);

    int src = 0;
    float w = 0.f;
    if (!small && !esc) {
        float fdeg = (float)deg;
        int off = min((int)floorf(u * fdeg), deg - 1);
        int eid = min(p0 + off, E - 1);
        src = __ldg(&src_idx[eid]);
        w = rsqrtf((float)max(__ldg(&g_counters[src]), 1)) * rsqrtf(fdeg);
    } else if (small && k < deg) {
        src = __ldg(&src_idx[p0 + k]);
        w = rsqrtf((float)max(__ldg(&g_counters[src]), 1)) *
            rsqrtf((float)max(deg, 1));
    }

    // Octet dedup — ALL lanes participate in the shuffles (no early return).
    int lane = threadIdx.x & 31;
    int base = lane & ~7;
    float wsum = 0.f;
    int first = k;
    #pragma unroll
    for (int j = 0; j < K; ++j) {
        int   sj = __shfl_sync(0xffffffffu, src, base + j);
        float wj = __shfl_sync(0xffffffffu, w,   base + j);
        if (sj == src) {
            wsum += wj;
            first = min(first, j);
        }
    }
    if (esc) {
        if (k == 0) g_pairs[t] = make_int2(-1, 0);
    } else {
        g_pairs[t] = (first == k) ? make_int2(src, __float_as_int(wsum))
                                  : make_int2(0, 0);
    }
    pdl_fire();
}

// Kernel 3: one warp per dst node, barrier-free. The ONLY dependent load is
// the 4 broadcast int4 pair loads; the path flag rides in pair0.x's sign.
__global__ void __launch_bounds__(256)
main_kernel(const float* __restrict__ h_src,
            const int* __restrict__ src_idx,
            float* __restrict__ out) {
    int warp = (blockIdx.x * blockDim.x + threadIdx.x) >> 5;  // grid exact
    int lane = threadIdx.x & 31;
    int n = warp;

    pdl_wait();                    // g_pairs valid beyond here

    const int4* pb = (const int4*)(g_pairs + n * K);
    int4 q0 = __ldg(&pb[0]);
    int4 q1 = __ldg(&pb[1]);
    int4 q2 = __ldg(&pb[2]);
    int4 q3 = __ldg(&pb[3]);

    float4 acc = make_float4(0.f, 0.f, 0.f, 0.f);

    if (q0.x >= 0) {
        int   srcs[K] = {q0.x, q0.z, q1.x, q1.z, q2.x, q2.z, q3.x, q3.z};
        float ws[K]   = {__int_as_float(q0.y), __int_as_float(q0.w),
                         __int_as_float(q1.y), __int_as_float(q1.w),
                         __int_as_float(q2.y), __int_as_float(q2.w),
                         __int_as_float(q3.y), __int_as_float(q3.w)};
        #pragma unroll
        for (int k = 0; k < K; ++k) {
            const float4* row = (const float4*)(h_src + (long long)srcs[k] * D);
            float4 v = __ldg(&row[lane]);
            float w = ws[k];
            acc.x += v.x * w; acc.y += v.y * w; acc.z += v.z * w; acc.w += v.w * w;
        }
        ((float4*)(out + (long long)n * D))[lane] = acc;
    } else {
        // Escape hatch (neg>0 && deg>K): full reduction over all edges.
        int p0 = __ldg(&g_ptr[n]);
        int p1 = __ldg(&g_ptr[n + 1]);
        int deg = p1 - p0;
        for (int e = p0; e < p1; ++e) {
            int s = __ldg(&src_idx[e]);
            float w = rsqrtf((float)max(__ldg(&g_counters[s]), 1));
            const float4* row = (const float4*)(h_src + (long long)s * D);
            float4 v = __ldg(&row[lane]);
            acc.x += v.x * w; acc.y += v.y * w; acc.z += v.z * w; acc.w += v.w * w;
        }
        float innorm = rsqrtf((float)max(deg, 1));
        float4 o;
        o.x = acc.x * innorm; o.y = acc.y * innorm;
        o.z = acc.z * innorm; o.w = acc.w * innorm;
        ((float4*)(out + (long long)n * D))[lane] = o;
    }
}

// Helper: launch with the PDL programmatic-stream-serialization attribute.
template <typename... Args>
static void launch_pdl(void (*kern)(Args...), dim3 grid, dim3 block,
                       Args... args) {
    cudaLaunchAttribute attr[1];
    attr[0].id = cudaLaunchAttributeProgrammaticStreamSerialization;
    attr[0].val.programmaticStreamSerializationAllowed = 1;
    cudaLaunchConfig_t cfg{};
    cfg.gridDim = grid;
    cfg.blockDim = block;
    cfg.dynamicSmemBytes = 0;
    cfg.stream = 0;
    cfg.attrs = attr;
    cfg.numAttrs = 1;
    cudaLaunchKernelEx(&cfg, kern, args...);
}

extern "C" void kernel_launch(void* const* d_in, const int* in_sizes, int n_in,
                              void* d_out, int out_size) {
    const float* h_src    = (const float*)d_in[0];
    // d_in[1] = h_dst : unused by the reference computation
    const float* unif     = (const float*)d_in[2];
    const int*   src_idx  = (const int*)d_in[3];
    const int*   dst_idx  = (const int*)d_in[4];
    const int*   category = (const int*)d_in[5];
    float* out = (float*)d_out;

    int E = in_sizes[3];
    int n_src = in_sizes[5];

    zero_scan_kernel<<<(N_SRC + N_DST + 255) / 256, 256>>>(category, n_src);
    launch_pdl(count_kernel, dim3((E + 255) / 256), dim3(256),
               src_idx, dst_idx, category, E);
    launch_pdl(prep_kernel, dim3((N_DST * K + 255) / 256), dim3(256),
               unif, src_idx, E);
    launch_pdl(main_kernel, dim3((N_DST * 32) / 256), dim3(256),
               h_src, src_idx, out);
}